// round 1
// baseline (speedup 1.0000x reference)
#include <cuda_runtime.h>
#include <math.h>

#define BB  512
#define SSL 128
#define HH  192
#define VV  256
#define PP  64
#define PHD 16
#define BT  4
#define NTH 192

__device__ __forceinline__ float gelu_exact(float x) {
    return 0.5f * x * (1.0f + erff(x * 0.70710678118654752440f));
}
__device__ __forceinline__ float sigmoidf_(float x) {
    return 1.0f / (1.0f + expf(-x));
}

// accumulate a 192-long K segment: W rows [ROW0, ROW0+192), N columns, column c
#define SEG_ACC(XS, WP, ROW0, NCOL)                                        \
    _Pragma("unroll 4")                                                    \
    for (int k = 0; k < 192; ++k) {                                        \
        float w  = (WP)[(ROW0 + k) * (NCOL) + c];                          \
        float4 x = *(const float4*)&(XS)[k][0];                            \
        acc.x = fmaf(w, x.x, acc.x); acc.y = fmaf(w, x.y, acc.y);          \
        acc.z = fmaf(w, x.z, acc.z); acc.w = fmaf(w, x.w, acc.w);          \
    }

__global__ __launch_bounds__(NTH, 1)
void spike_recurrence_kernel(
    const int*   __restrict__ input_ids,
    const float* __restrict__ emb,
    const float* __restrict__ sel_W,  const float* __restrict__ sel_b,
    const float* __restrict__ patch_values,
    const float* __restrict__ bind_W1, const float* __restrict__ bind_b1,
    const float* __restrict__ bind_W2, const float* __restrict__ bind_b2,
    const float* __restrict__ phase_embed,
    const float* __restrict__ router_W, const float* __restrict__ router_b,
    const float* __restrict__ succ_W1, const float* __restrict__ succ_b1,
    const float* __restrict__ succ_W2, const float* __restrict__ succ_b2,
    const float* __restrict__ gate_W1, const float* __restrict__ gate_b1,
    const float* __restrict__ gate_W2, const float* __restrict__ gate_b2,
    const float* __restrict__ ln_g,   const float* __restrict__ ln_b,
    const float* __restrict__ dec_W,
    float* __restrict__ out)
{
    __shared__ __align__(16) float tok  [HH][BT];
    __shared__ __align__(16) float prevb[HH][BT];
    __shared__ __align__(16) float patch[HH][BT];
    __shared__ __align__(16) float sec  [HH][BT];
    __shared__ __align__(16) float phs  [HH][BT];
    __shared__ __align__(16) float succ [HH][BT];
    __shared__ __align__(16) float htmp [HH][BT];
    __shared__ __align__(16) float pwb  [PP][BT];
    __shared__ __align__(16) float rlog [PHD][BT];
    __shared__ __align__(16) float phwb [PHD][BT];
    __shared__ __align__(16) float partbuf[3 * 64 * BT];
    __shared__ float gatev[BT];
    __shared__ float lnmean[BT], lnrstd[BT];
    __shared__ int   sidx[BT][SSL];

    const int t     = threadIdx.x;
    const int lane  = t & 31;
    const int warp  = t >> 5;
    const int bbase = blockIdx.x * BT;

    // preload this CTA's token ids for all steps
    for (int i = t; i < BT * SSL; i += NTH) {
        int r = i / SSL, ss = i % SSL;
        sidx[r][ss] = input_ids[(bbase + r) * SSL + ss];
    }
    // prev_0 = 0
    *(float4*)&prevb[t][0] = make_float4(0.f, 0.f, 0.f, 0.f);
    __syncthreads();

    const size_t OFF_HID = (size_t)BB * SSL * VV;
    const size_t OFF_PW  = OFF_HID + (size_t)BB * SSL * HH;
    const size_t OFF_PHW = OFF_PW  + (size_t)BB * SSL * PP;
    const size_t OFF_GT  = OFF_PHW + (size_t)BB * SSL * PHD;

    for (int s = 0; s < SSL; ++s) {
        // ---- token embeddings -------------------------------------------
        {
            #pragma unroll
            for (int r = 0; r < BT; ++r)
                tok[t][r] = emb[(size_t)sidx[r][s] * HH + t];
        }
        __syncthreads();

        // ---- patch selector: softmax([tok,prev] @ sel_W + b) ------------
        {
            int c = t % 64, p = t / 64;   // 3 K-partials of 128 over K=384
            float4 acc = make_float4(0.f, 0.f, 0.f, 0.f);
            if (p == 0) {
                #pragma unroll 4
                for (int k = 0; k < 128; ++k) {
                    float w = sel_W[k * PP + c];
                    float4 x = *(const float4*)&tok[k][0];
                    acc.x = fmaf(w, x.x, acc.x); acc.y = fmaf(w, x.y, acc.y);
                    acc.z = fmaf(w, x.z, acc.z); acc.w = fmaf(w, x.w, acc.w);
                }
            } else if (p == 1) {
                #pragma unroll 4
                for (int k = 0; k < 64; ++k) {
                    float w = sel_W[(128 + k) * PP + c];
                    float4 x = *(const float4*)&tok[128 + k][0];
                    acc.x = fmaf(w, x.x, acc.x); acc.y = fmaf(w, x.y, acc.y);
                    acc.z = fmaf(w, x.z, acc.z); acc.w = fmaf(w, x.w, acc.w);
                }
                #pragma unroll 4
                for (int k = 0; k < 64; ++k) {
                    float w = sel_W[(192 + k) * PP + c];
                    float4 x = *(const float4*)&prevb[k][0];
                    acc.x = fmaf(w, x.x, acc.x); acc.y = fmaf(w, x.y, acc.y);
                    acc.z = fmaf(w, x.z, acc.z); acc.w = fmaf(w, x.w, acc.w);
                }
            } else {
                #pragma unroll 4
                for (int k = 0; k < 128; ++k) {
                    float w = sel_W[(256 + k) * PP + c];
                    float4 x = *(const float4*)&prevb[64 + k][0];
                    acc.x = fmaf(w, x.x, acc.x); acc.y = fmaf(w, x.y, acc.y);
                    acc.z = fmaf(w, x.z, acc.z); acc.w = fmaf(w, x.w, acc.w);
                }
            }
            *(float4*)&partbuf[(p * 64 + c) * BT] = acc;
        }
        __syncthreads();
        if (t < 64) {
            float4 a0 = *(float4*)&partbuf[t * BT];
            float4 a1 = *(float4*)&partbuf[(64 + t) * BT];
            float4 a2 = *(float4*)&partbuf[(128 + t) * BT];
            float bias = sel_b[t];
            float4 l;
            l.x = a0.x + a1.x + a2.x + bias;
            l.y = a0.y + a1.y + a2.y + bias;
            l.z = a0.z + a1.z + a2.z + bias;
            l.w = a0.w + a1.w + a2.w + bias;
            *(float4*)&pwb[t][0] = l;
        }
        __syncthreads();
        if (warp < BT) {  // softmax over 64, one warp per batch row
            int r = warp;
            float v0 = pwb[lane][r], v1 = pwb[lane + 32][r];
            float m = fmaxf(v0, v1);
            #pragma unroll
            for (int o = 16; o > 0; o >>= 1) m = fmaxf(m, __shfl_xor_sync(0xffffffffu, m, o));
            float e0 = expf(v0 - m), e1 = expf(v1 - m);
            float sm = e0 + e1;
            #pragma unroll
            for (int o = 16; o > 0; o >>= 1) sm += __shfl_xor_sync(0xffffffffu, sm, o);
            float inv = 1.0f / sm;
            e0 *= inv; e1 *= inv;
            pwb[lane][r] = e0; pwb[lane + 32][r] = e1;
            size_t ob = OFF_PW + ((size_t)(bbase + r) * SSL + s) * PP;
            out[ob + lane] = e0; out[ob + lane + 32] = e1;
        }
        __syncthreads();

        // ---- patch = pw @ patch_values ----------------------------------
        {
            int c = t;
            float4 acc = make_float4(0.f, 0.f, 0.f, 0.f);
            #pragma unroll 4
            for (int k = 0; k < PP; ++k) {
                float w = patch_values[k * HH + c];
                float4 x = *(const float4*)&pwb[k][0];
                acc.x = fmaf(w, x.x, acc.x); acc.y = fmaf(w, x.y, acc.y);
                acc.z = fmaf(w, x.z, acc.z); acc.w = fmaf(w, x.w, acc.w);
            }
            *(float4*)&patch[c][0] = acc;
        }
        __syncthreads();

        // ---- section binder ---------------------------------------------
        {
            int c = t;
            float4 acc = make_float4(0.f, 0.f, 0.f, 0.f);
            SEG_ACC(tok,   bind_W1,   0, HH)
            SEG_ACC(patch, bind_W1, 192, HH)
            SEG_ACC(prevb, bind_W1, 384, HH)
            float b1 = bind_b1[c];
            float4 h;
            h.x = gelu_exact(acc.x + b1); h.y = gelu_exact(acc.y + b1);
            h.z = gelu_exact(acc.z + b1); h.w = gelu_exact(acc.w + b1);
            *(float4*)&htmp[c][0] = h;
        }
        __syncthreads();
        {
            int c = t;
            float4 acc = make_float4(0.f, 0.f, 0.f, 0.f);
            SEG_ACC(htmp, bind_W2, 0, HH)
            float b2 = bind_b2[c];
            float4 h;
            h.x = tanhf(acc.x + b2); h.y = tanhf(acc.y + b2);
            h.z = tanhf(acc.z + b2); h.w = tanhf(acc.w + b2);
            *(float4*)&sec[c][0] = h;
        }
        __syncthreads();

        // ---- phase router: softmax([sec,prev] @ router_W + b) -----------
        if (t < 128) {
            int c = t & 15, p = t >> 4;   // 8 partials of 48 over K=384
            float4 acc = make_float4(0.f, 0.f, 0.f, 0.f);
            #pragma unroll 4
            for (int kk = 0; kk < 48; ++kk) {
                int row = p * 48 + kk;
                float w = router_W[row * PHD + c];
                const float* xp = (row < 192) ? &sec[row][0] : &prevb[row - 192][0];
                float4 x = *(const float4*)xp;
                acc.x = fmaf(w, x.x, acc.x); acc.y = fmaf(w, x.y, acc.y);
                acc.z = fmaf(w, x.z, acc.z); acc.w = fmaf(w, x.w, acc.w);
            }
            *(float4*)&partbuf[(p * 16 + c) * BT] = acc;
        }
        __syncthreads();
        if (t < 64) {
            int c = t & 15, r = t >> 4;
            float sum = router_b[c];
            #pragma unroll
            for (int p = 0; p < 8; ++p) sum += partbuf[(p * 16 + c) * BT + r];
            rlog[c][r] = sum;
        }
        __syncthreads();
        if (t < BT) {
            int r = t;
            float m = -1e30f;
            #pragma unroll
            for (int c = 0; c < PHD; ++c) m = fmaxf(m, rlog[c][r]);
            float sm = 0.f;
            float e[PHD];
            #pragma unroll
            for (int c = 0; c < PHD; ++c) { e[c] = expf(rlog[c][r] - m); sm += e[c]; }
            float inv = 1.0f / sm;
            size_t ob = OFF_PHW + ((size_t)(bbase + r) * SSL + s) * PHD;
            #pragma unroll
            for (int c = 0; c < PHD; ++c) {
                float v = e[c] * inv;
                phwb[c][r] = v;
                out[ob + c] = v;
            }
        }
        __syncthreads();

        // ---- phs = phw @ phase_embed ------------------------------------
        {
            int c = t;
            float4 acc = make_float4(0.f, 0.f, 0.f, 0.f);
            #pragma unroll
            for (int k = 0; k < PHD; ++k) {
                float w = phase_embed[k * HH + c];
                float4 x = *(const float4*)&phwb[k][0];
                acc.x = fmaf(w, x.x, acc.x); acc.y = fmaf(w, x.y, acc.y);
                acc.z = fmaf(w, x.z, acc.z); acc.w = fmaf(w, x.w, acc.w);
            }
            *(float4*)&phs[c][0] = acc;
        }
        __syncthreads();

        // ---- successor ----------------------------------------------------
        {
            int c = t;
            float4 acc = make_float4(0.f, 0.f, 0.f, 0.f);
            SEG_ACC(sec,   succ_W1,   0, HH)
            SEG_ACC(patch, succ_W1, 192, HH)
            SEG_ACC(phs,   succ_W1, 384, HH)
            float b1 = succ_b1[c];
            float4 h;
            h.x = gelu_exact(acc.x + b1); h.y = gelu_exact(acc.y + b1);
            h.z = gelu_exact(acc.z + b1); h.w = gelu_exact(acc.w + b1);
            *(float4*)&htmp[c][0] = h;
        }
        __syncthreads();
        {
            int c = t;
            float4 acc = make_float4(0.f, 0.f, 0.f, 0.f);
            SEG_ACC(htmp, succ_W2, 0, HH)
            float b2 = succ_b2[c];
            float4 h;
            h.x = tanhf(acc.x + b2); h.y = tanhf(acc.y + b2);
            h.z = tanhf(acc.z + b2); h.w = tanhf(acc.w + b2);
            *(float4*)&succ[c][0] = h;
        }
        __syncthreads();

        // ---- gate ---------------------------------------------------------
        {
            int c = t;
            float4 acc = make_float4(0.f, 0.f, 0.f, 0.f);
            SEG_ACC(succ,  gate_W1,   0, HH)
            SEG_ACC(prevb, gate_W1, 192, HH)
            float b1 = gate_b1[c];
            float w2 = gate_W2[c];
            float4 h;
            h.x = gelu_exact(acc.x + b1) * w2; h.y = gelu_exact(acc.y + b1) * w2;
            h.z = gelu_exact(acc.z + b1) * w2; h.w = gelu_exact(acc.w + b1) * w2;
            *(float4*)&htmp[c][0] = h;
        }
        __syncthreads();
        if (warp < BT) {
            int r = warp;
            float sg = 0.f;
            #pragma unroll
            for (int j = 0; j < 6; ++j) sg += htmp[lane + 32 * j][r];
            #pragma unroll
            for (int o = 16; o > 0; o >>= 1) sg += __shfl_xor_sync(0xffffffffu, sg, o);
            if (lane == 0) {
                float gv = sigmoidf_(sg + gate_b2[0]);
                gatev[r] = gv;
                out[OFF_GT + (size_t)(bbase + r) * SSL + s] = gv;
            }
        }
        __syncthreads();

        // ---- hidden blend + LayerNorm -------------------------------------
        {
            int c = t;
            float4 sv = *(const float4*)&succ[c][0];
            float4 pv = *(const float4*)&prevb[c][0];
            float4 h;
            h.x = gatev[0] * sv.x + (1.f - gatev[0]) * pv.x;
            h.y = gatev[1] * sv.y + (1.f - gatev[1]) * pv.y;
            h.z = gatev[2] * sv.z + (1.f - gatev[2]) * pv.z;
            h.w = gatev[3] * sv.w + (1.f - gatev[3]) * pv.w;
            *(float4*)&htmp[c][0] = h;
        }
        __syncthreads();
        if (warp < BT) {
            int r = warp;
            float sm = 0.f, sq = 0.f;
            #pragma unroll
            for (int j = 0; j < 6; ++j) {
                float v = htmp[lane + 32 * j][r];
                sm += v; sq += v * v;
            }
            #pragma unroll
            for (int o = 16; o > 0; o >>= 1) {
                sm += __shfl_xor_sync(0xffffffffu, sm, o);
                sq += __shfl_xor_sync(0xffffffffu, sq, o);
            }
            if (lane == 0) {
                float mean = sm * (1.0f / HH);
                float var  = sq * (1.0f / HH) - mean * mean;
                lnmean[r] = mean;
                lnrstd[r] = rsqrtf(var + 1e-5f);
            }
        }
        __syncthreads();
        {
            int c = t;
            float g = ln_g[c], bb = ln_b[c];
            float4 h = *(const float4*)&htmp[c][0];
            float4 o;
            o.x = (h.x - lnmean[0]) * lnrstd[0] * g + bb;
            o.y = (h.y - lnmean[1]) * lnrstd[1] * g + bb;
            o.z = (h.z - lnmean[2]) * lnrstd[2] * g + bb;
            o.w = (h.w - lnmean[3]) * lnrstd[3] * g + bb;
            *(float4*)&prevb[c][0] = o;   // carry for next step
            #pragma unroll
            for (int r = 0; r < BT; ++r)
                out[OFF_HID + ((size_t)(bbase + r) * SSL + s) * HH + c] =
                    (r == 0) ? o.x : (r == 1) ? o.y : (r == 2) ? o.z : o.w;
        }
        __syncthreads();

        // ---- decoder logits -----------------------------------------------
        {
            int c0 = t;
            bool two = (t < 64);
            int c1 = 192 + t;
            float4 acc0 = make_float4(0.f, 0.f, 0.f, 0.f);
            float4 acc1 = make_float4(0.f, 0.f, 0.f, 0.f);
            #pragma unroll 4
            for (int k = 0; k < HH; ++k) {
                float4 x = *(const float4*)&prevb[k][0];
                float w0 = dec_W[k * VV + c0];
                acc0.x = fmaf(w0, x.x, acc0.x); acc0.y = fmaf(w0, x.y, acc0.y);
                acc0.z = fmaf(w0, x.z, acc0.z); acc0.w = fmaf(w0, x.w, acc0.w);
                if (two) {
                    float w1 = dec_W[k * VV + c1];
                    acc1.x = fmaf(w1, x.x, acc1.x); acc1.y = fmaf(w1, x.y, acc1.y);
                    acc1.z = fmaf(w1, x.z, acc1.z); acc1.w = fmaf(w1, x.w, acc1.w);
                }
            }
            #pragma unroll
            for (int r = 0; r < BT; ++r) {
                size_t ob = ((size_t)(bbase + r) * SSL + s) * VV;
                float v0 = (r == 0) ? acc0.x : (r == 1) ? acc0.y : (r == 2) ? acc0.z : acc0.w;
                out[ob + c0] = v0;
                if (two) {
                    float v1 = (r == 0) ? acc1.x : (r == 1) ? acc1.y : (r == 2) ? acc1.z : acc1.w;
                    out[ob + c1] = v1;
                }
            }
        }
        __syncthreads();
    }
}

extern "C" void kernel_launch(void* const* d_in, const int* in_sizes, int n_in,
                              void* d_out, int out_size) {
    const int*   input_ids    = (const int*)  d_in[0];
    const float* emb          = (const float*)d_in[1];
    const float* sel_W        = (const float*)d_in[2];
    const float* sel_b        = (const float*)d_in[3];
    const float* patch_values = (const float*)d_in[4];
    const float* bind_W1      = (const float*)d_in[5];
    const float* bind_b1      = (const float*)d_in[6];
    const float* bind_W2      = (const float*)d_in[7];
    const float* bind_b2      = (const float*)d_in[8];
    const float* phase_embed  = (const float*)d_in[9];
    const float* router_W     = (const float*)d_in[10];
    const float* router_b     = (const float*)d_in[11];
    const float* succ_W1      = (const float*)d_in[12];
    const float* succ_b1      = (const float*)d_in[13];
    const float* succ_W2      = (const float*)d_in[14];
    const float* succ_b2      = (const float*)d_in[15];
    const float* gate_W1      = (const float*)d_in[16];
    const float* gate_b1      = (const float*)d_in[17];
    const float* gate_W2      = (const float*)d_in[18];
    const float* gate_b2      = (const float*)d_in[19];
    const float* ln_g         = (const float*)d_in[20];
    const float* ln_b         = (const float*)d_in[21];
    const float* dec_W        = (const float*)d_in[22];
    float* out = (float*)d_out;

    spike_recurrence_kernel<<<BB / BT, NTH>>>(
        input_ids, emb, sel_W, sel_b, patch_values,
        bind_W1, bind_b1, bind_W2, bind_b2,
        phase_embed, router_W, router_b,
        succ_W1, succ_b1, succ_W2, succ_b2,
        gate_W1, gate_b1, gate_W2, gate_b2,
        ln_g, ln_b, dec_W, out);
}

// round 2
// speedup vs baseline: 4.6804x; 4.6804x over previous
#include <cuda_runtime.h>
#include <math.h>

#define BB  512
#define SSL 128
#define HH  192
#define VV  256
#define PP  64
#define PHD 16
#define BT  4
#define NTH 384

struct SMLayout {
    float tok  [HH][BT];
    float prevb[HH][BT];
    float patch[HH][BT];
    float sec  [HH][BT];
    float phs  [HH][BT];
    float succ [HH][BT];
    float htmp [HH][BT];
    float4 partbuf[NTH][4];     // per-thread 4-col x 4-row partials
    float pwb [PP][BT];
    float rlog[PHD][BT];
    float phwb[PHD][BT];
    float gatev[BT];
    float lnmean[BT], lnrstd[BT];
    int   sidx[BT][SSL];
};

__device__ __forceinline__ float gelu_exact(float x) {
    return 0.5f * x * (1.0f + erff(x * 0.70710678118654752440f));
}
__device__ __forceinline__ float sigmoidf_(float x) {
    return 1.0f / (1.0f + expf(-x));
}
__device__ __forceinline__ void fma4(float4& a, float w, const float4& x) {
    a.x = fmaf(w, x.x, a.x); a.y = fmaf(w, x.y, a.y);
    a.z = fmaf(w, x.z, a.z); a.w = fmaf(w, x.w, a.w);
}

// Accumulate NIT rows: weights W[(wrow0+k)*Ns + c0 .. +3], activations X[xrow0+k][0..3]
template<int NIT>
__device__ __forceinline__ void seg4(
    float4& A0, float4& A1, float4& A2, float4& A3,
    const float (*__restrict__ X)[BT], const float* __restrict__ W,
    int xrow0, int wrow0, int Ns, int c0)
{
    #pragma unroll 8
    for (int k = 0; k < NIT; ++k) {
        float4 w = *(const float4*)(W + (size_t)(wrow0 + k) * Ns + c0);
        float4 x = *(const float4*)&X[xrow0 + k][0];
        fma4(A0, w.x, x); fma4(A1, w.y, x); fma4(A2, w.z, x); fma4(A3, w.w, x);
    }
}

#define PART_STORE()                                                \
    s->partbuf[t][0] = A0; s->partbuf[t][1] = A1;                   \
    s->partbuf[t][2] = A2; s->partbuf[t][3] = A3;

#define REDUCE_SUM(NN, NGP, PCH)                                    \
    int gg = t >> 2, cc = t & 3;                                    \
    float4 sv = s->partbuf[gg][cc];                                 \
    _Pragma("unroll")                                               \
    for (int pp = 1; pp < (PCH); ++pp) {                            \
        float4 v = s->partbuf[pp * (NGP) + gg][cc];                 \
        sv.x += v.x; sv.y += v.y; sv.z += v.z; sv.w += v.w;         \
    }

__global__ __launch_bounds__(NTH, 1)
void spike_recurrence_kernel(
    const int*   __restrict__ input_ids,
    const float* __restrict__ emb,
    const float* __restrict__ sel_W,  const float* __restrict__ sel_b,
    const float* __restrict__ patch_values,
    const float* __restrict__ bind_W1, const float* __restrict__ bind_b1,
    const float* __restrict__ bind_W2, const float* __restrict__ bind_b2,
    const float* __restrict__ phase_embed,
    const float* __restrict__ router_W, const float* __restrict__ router_b,
    const float* __restrict__ succ_W1, const float* __restrict__ succ_b1,
    const float* __restrict__ succ_W2, const float* __restrict__ succ_b2,
    const float* __restrict__ gate_W1, const float* __restrict__ gate_b1,
    const float* __restrict__ gate_W2, const float* __restrict__ gate_b2,
    const float* __restrict__ ln_g,   const float* __restrict__ ln_b,
    const float* __restrict__ dec_W,
    float* __restrict__ out)
{
    extern __shared__ char smraw[];
    SMLayout* s = (SMLayout*)smraw;

    const int t    = threadIdx.x;
    const int lane = t & 31;
    const int warp = t >> 5;
    const int bbase = blockIdx.x * BT;
    const float4 z4 = make_float4(0.f, 0.f, 0.f, 0.f);

    for (int i = t; i < BT * SSL; i += NTH) {
        int r = i / SSL, ss = i % SSL;
        s->sidx[r][ss] = input_ids[(bbase + r) * SSL + ss];
    }
    if (t < HH) *(float4*)&s->prevb[t][0] = z4;
    __syncthreads();

    const size_t OFF_HID = (size_t)BB * SSL * VV;
    const size_t OFF_PW  = OFF_HID + (size_t)BB * SSL * HH;
    const size_t OFF_PHW = OFF_PW  + (size_t)BB * SSL * PP;
    const size_t OFF_GT  = OFF_PHW + (size_t)BB * SSL * PHD;

    for (int st = 0; st < SSL; ++st) {
        // ---- token embedding gather ------------------------------------
        for (int i = t; i < HH * BT; i += NTH) {
            int r = i / HH, c = i % HH;
            s->tok[c][r] = emb[(size_t)s->sidx[r][st] * HH + c];
        }
        __syncthreads();

        // ---- sel: [tok,prev] @ sel_W  (N=64, NG=16, P=24, kpp=8) --------
        {
            int g = t % 16, p = t / 16, c0 = 4 * g;
            float4 A0 = z4, A1 = z4, A2 = z4, A3 = z4;
            seg4<8>(A0, A1, A2, A3, s->tok,   sel_W, p * 8,       p * 8, PP, c0);
            seg4<8>(A0, A1, A2, A3, s->prevb, sel_W, p * 8, 192 + p * 8, PP, c0);
            PART_STORE();
        }
        __syncthreads();
        if (t < PP) {
            REDUCE_SUM(PP, 16, 24);
            float bias = sel_b[t];
            sv.x += bias; sv.y += bias; sv.z += bias; sv.w += bias;
            *(float4*)&s->pwb[t][0] = sv;
        }
        __syncthreads();
        if (warp < BT) {  // softmax over 64, one warp per batch row
            int r = warp;
            float v0 = s->pwb[lane][r], v1 = s->pwb[lane + 32][r];
            float m = fmaxf(v0, v1);
            #pragma unroll
            for (int o = 16; o > 0; o >>= 1) m = fmaxf(m, __shfl_xor_sync(0xffffffffu, m, o));
            float e0 = expf(v0 - m), e1 = expf(v1 - m);
            float sm = e0 + e1;
            #pragma unroll
            for (int o = 16; o > 0; o >>= 1) sm += __shfl_xor_sync(0xffffffffu, sm, o);
            float inv = 1.0f / sm;
            e0 *= inv; e1 *= inv;
            s->pwb[lane][r] = e0; s->pwb[lane + 32][r] = e1;
            size_t ob = OFF_PW + ((size_t)(bbase + r) * SSL + st) * PP;
            out[ob + lane] = e0; out[ob + lane + 32] = e1;
        }
        __syncthreads();

        // ---- patch = pw @ patch_values  (N=192, NG=48, P=8, kpp=8) ------
        {
            int g = t % 48, p = t / 48, c0 = 4 * g;
            float4 A0 = z4, A1 = z4, A2 = z4, A3 = z4;
            seg4<8>(A0, A1, A2, A3, s->pwb, patch_values, p * 8, p * 8, HH, c0);
            PART_STORE();
        }
        __syncthreads();
        if (t < HH) {
            REDUCE_SUM(HH, 48, 8);
            *(float4*)&s->patch[t][0] = sv;
        }
        __syncthreads();

        // ---- bind1: [tok,patch,prev] @ bind_W1 -> gelu  (kpp=24) --------
        {
            int g = t % 48, p = t / 48, c0 = 4 * g;
            float4 A0 = z4, A1 = z4, A2 = z4, A3 = z4;
            seg4<24>(A0, A1, A2, A3, s->tok,   bind_W1, p * 24,        p * 24, HH, c0);
            seg4<24>(A0, A1, A2, A3, s->patch, bind_W1, p * 24,  192 + p * 24, HH, c0);
            seg4<24>(A0, A1, A2, A3, s->prevb, bind_W1, p * 24,  384 + p * 24, HH, c0);
            PART_STORE();
        }
        __syncthreads();
        if (t < HH) {
            REDUCE_SUM(HH, 48, 8);
            float b1 = bind_b1[t];
            float4 h;
            h.x = gelu_exact(sv.x + b1); h.y = gelu_exact(sv.y + b1);
            h.z = gelu_exact(sv.z + b1); h.w = gelu_exact(sv.w + b1);
            *(float4*)&s->htmp[t][0] = h;
        }
        __syncthreads();

        // ---- bind2: htmp @ bind_W2 -> tanh ------------------------------
        {
            int g = t % 48, p = t / 48, c0 = 4 * g;
            float4 A0 = z4, A1 = z4, A2 = z4, A3 = z4;
            seg4<24>(A0, A1, A2, A3, s->htmp, bind_W2, p * 24, p * 24, HH, c0);
            PART_STORE();
        }
        __syncthreads();
        if (t < HH) {
            REDUCE_SUM(HH, 48, 8);
            float b2 = bind_b2[t];
            float4 h;
            h.x = tanhf(sv.x + b2); h.y = tanhf(sv.y + b2);
            h.z = tanhf(sv.z + b2); h.w = tanhf(sv.w + b2);
            *(float4*)&s->sec[t][0] = h;
        }
        __syncthreads();

        // ---- router: [sec,prev] @ router_W  (N=16, NG=4, P=96, kpp=2) ---
        {
            int g = t % 4, p = t / 4, c0 = 4 * g;
            float4 A0 = z4, A1 = z4, A2 = z4, A3 = z4;
            seg4<2>(A0, A1, A2, A3, s->sec,   router_W, p * 2,       p * 2, PHD, c0);
            seg4<2>(A0, A1, A2, A3, s->prevb, router_W, p * 2, 192 + p * 2, PHD, c0);
            PART_STORE();
        }
        __syncthreads();
        if (t < PHD) {
            REDUCE_SUM(PHD, 4, 96);
            float bias = router_b[t];
            sv.x += bias; sv.y += bias; sv.z += bias; sv.w += bias;
            *(float4*)&s->rlog[t][0] = sv;
        }
        __syncthreads();
        if (t < BT) {
            int r = t;
            float m = -1e30f;
            #pragma unroll
            for (int c = 0; c < PHD; ++c) m = fmaxf(m, s->rlog[c][r]);
            float sm = 0.f;
            float e[PHD];
            #pragma unroll
            for (int c = 0; c < PHD; ++c) { e[c] = expf(s->rlog[c][r] - m); sm += e[c]; }
            float inv = 1.0f / sm;
            size_t ob = OFF_PHW + ((size_t)(bbase + r) * SSL + st) * PHD;
            #pragma unroll
            for (int c = 0; c < PHD; ++c) {
                float v = e[c] * inv;
                s->phwb[c][r] = v;
                out[ob + c] = v;
            }
        }
        __syncthreads();

        // ---- phs = phw @ phase_embed  (N=192, K=16, kpp=2) --------------
        {
            int g = t % 48, p = t / 48, c0 = 4 * g;
            float4 A0 = z4, A1 = z4, A2 = z4, A3 = z4;
            seg4<2>(A0, A1, A2, A3, s->phwb, phase_embed, p * 2, p * 2, HH, c0);
            PART_STORE();
        }
        __syncthreads();
        if (t < HH) {
            REDUCE_SUM(HH, 48, 8);
            *(float4*)&s->phs[t][0] = sv;
        }
        __syncthreads();

        // ---- succ1: [sec,patch,phs] @ succ_W1 -> gelu --------------------
        {
            int g = t % 48, p = t / 48, c0 = 4 * g;
            float4 A0 = z4, A1 = z4, A2 = z4, A3 = z4;
            seg4<24>(A0, A1, A2, A3, s->sec,   succ_W1, p * 24,        p * 24, HH, c0);
            seg4<24>(A0, A1, A2, A3, s->patch, succ_W1, p * 24,  192 + p * 24, HH, c0);
            seg4<24>(A0, A1, A2, A3, s->phs,   succ_W1, p * 24,  384 + p * 24, HH, c0);
            PART_STORE();
        }
        __syncthreads();
        if (t < HH) {
            REDUCE_SUM(HH, 48, 8);
            float b1 = succ_b1[t];
            float4 h;
            h.x = gelu_exact(sv.x + b1); h.y = gelu_exact(sv.y + b1);
            h.z = gelu_exact(sv.z + b1); h.w = gelu_exact(sv.w + b1);
            *(float4*)&s->htmp[t][0] = h;
        }
        __syncthreads();

        // ---- succ2: htmp @ succ_W2 -> tanh -------------------------------
        {
            int g = t % 48, p = t / 48, c0 = 4 * g;
            float4 A0 = z4, A1 = z4, A2 = z4, A3 = z4;
            seg4<24>(A0, A1, A2, A3, s->htmp, succ_W2, p * 24, p * 24, HH, c0);
            PART_STORE();
        }
        __syncthreads();
        if (t < HH) {
            REDUCE_SUM(HH, 48, 8);
            float b2 = succ_b2[t];
            float4 h;
            h.x = tanhf(sv.x + b2); h.y = tanhf(sv.y + b2);
            h.z = tanhf(sv.z + b2); h.w = tanhf(sv.w + b2);
            *(float4*)&s->succ[t][0] = h;
        }
        __syncthreads();

        // ---- gate: [succ,prev] @ gate_W1 -> gelu * gate_W2 ---------------
        {
            int g = t % 48, p = t / 48, c0 = 4 * g;
            float4 A0 = z4, A1 = z4, A2 = z4, A3 = z4;
            seg4<24>(A0, A1, A2, A3, s->succ,  gate_W1, p * 24,        p * 24, HH, c0);
            seg4<24>(A0, A1, A2, A3, s->prevb, gate_W1, p * 24,  192 + p * 24, HH, c0);
            PART_STORE();
        }
        __syncthreads();
        if (t < HH) {
            REDUCE_SUM(HH, 48, 8);
            float b1 = gate_b1[t];
            float w2 = gate_W2[t];
            float4 h;
            h.x = gelu_exact(sv.x + b1) * w2; h.y = gelu_exact(sv.y + b1) * w2;
            h.z = gelu_exact(sv.z + b1) * w2; h.w = gelu_exact(sv.w + b1) * w2;
            *(float4*)&s->htmp[t][0] = h;
        }
        __syncthreads();
        if (warp < BT) {
            int r = warp;
            float sg = 0.f;
            #pragma unroll
            for (int j = 0; j < 6; ++j) sg += s->htmp[lane + 32 * j][r];
            #pragma unroll
            for (int o = 16; o > 0; o >>= 1) sg += __shfl_xor_sync(0xffffffffu, sg, o);
            if (lane == 0) {
                float gv = sigmoidf_(sg + gate_b2[0]);
                s->gatev[r] = gv;
                out[OFF_GT + (size_t)(bbase + r) * SSL + st] = gv;
            }
        }
        __syncthreads();

        // ---- hidden blend + LayerNorm -------------------------------------
        if (t < HH) {
            float4 svv = *(const float4*)&s->succ[t][0];
            float4 pv  = *(const float4*)&s->prevb[t][0];
            float4 h;
            h.x = s->gatev[0] * svv.x + (1.f - s->gatev[0]) * pv.x;
            h.y = s->gatev[1] * svv.y + (1.f - s->gatev[1]) * pv.y;
            h.z = s->gatev[2] * svv.z + (1.f - s->gatev[2]) * pv.z;
            h.w = s->gatev[3] * svv.w + (1.f - s->gatev[3]) * pv.w;
            *(float4*)&s->htmp[t][0] = h;
        }
        __syncthreads();
        if (warp < BT) {
            int r = warp;
            float sm = 0.f, sq = 0.f;
            #pragma unroll
            for (int j = 0; j < 6; ++j) {
                float v = s->htmp[lane + 32 * j][r];
                sm += v; sq += v * v;
            }
            #pragma unroll
            for (int o = 16; o > 0; o >>= 1) {
                sm += __shfl_xor_sync(0xffffffffu, sm, o);
                sq += __shfl_xor_sync(0xffffffffu, sq, o);
            }
            if (lane == 0) {
                float mean = sm * (1.0f / HH);
                float var  = sq * (1.0f / HH) - mean * mean;
                s->lnmean[r] = mean;
                s->lnrstd[r] = rsqrtf(var + 1e-5f);
            }
        }
        __syncthreads();
        if (t < HH) {
            float g = ln_g[t], bb = ln_b[t];
            float4 h = *(const float4*)&s->htmp[t][0];
            float4 o;
            o.x = (h.x - s->lnmean[0]) * s->lnrstd[0] * g + bb;
            o.y = (h.y - s->lnmean[1]) * s->lnrstd[1] * g + bb;
            o.z = (h.z - s->lnmean[2]) * s->lnrstd[2] * g + bb;
            o.w = (h.w - s->lnmean[3]) * s->lnrstd[3] * g + bb;
            *(float4*)&s->prevb[t][0] = o;   // carry for next step
            #pragma unroll
            for (int r = 0; r < BT; ++r)
                out[OFF_HID + ((size_t)(bbase + r) * SSL + st) * HH + t] =
                    (r == 0) ? o.x : (r == 1) ? o.y : (r == 2) ? o.z : o.w;
        }
        __syncthreads();

        // ---- decoder logits  (N=256, NG=64, P=6, kpp=32) -----------------
        {
            int g = t % 64, p = t / 64, c0 = 4 * g;
            float4 A0 = z4, A1 = z4, A2 = z4, A3 = z4;
            seg4<32>(A0, A1, A2, A3, s->prevb, dec_W, p * 32, p * 32, VV, c0);
            PART_STORE();
        }
        __syncthreads();
        if (t < VV) {
            REDUCE_SUM(VV, 64, 6);
            #pragma unroll
            for (int r = 0; r < BT; ++r) {
                size_t ob = ((size_t)(bbase + r) * SSL + st) * VV;
                float v = (r == 0) ? sv.x : (r == 1) ? sv.y : (r == 2) ? sv.z : sv.w;
                out[ob + t] = v;
            }
        }
        __syncthreads();
    }
}

extern "C" void kernel_launch(void* const* d_in, const int* in_sizes, int n_in,
                              void* d_out, int out_size) {
    const int*   input_ids    = (const int*)  d_in[0];
    const float* emb          = (const float*)d_in[1];
    const float* sel_W        = (const float*)d_in[2];
    const float* sel_b        = (const float*)d_in[3];
    const float* patch_values = (const float*)d_in[4];
    const float* bind_W1      = (const float*)d_in[5];
    const float* bind_b1      = (const float*)d_in[6];
    const float* bind_W2      = (const float*)d_in[7];
    const float* bind_b2      = (const float*)d_in[8];
    const float* phase_embed  = (const float*)d_in[9];
    const float* router_W     = (const float*)d_in[10];
    const float* router_b     = (const float*)d_in[11];
    const float* succ_W1      = (const float*)d_in[12];
    const float* succ_b1      = (const float*)d_in[13];
    const float* succ_W2      = (const float*)d_in[14];
    const float* succ_b2      = (const float*)d_in[15];
    const float* gate_W1      = (const float*)d_in[16];
    const float* gate_b1      = (const float*)d_in[17];
    const float* gate_W2      = (const float*)d_in[18];
    const float* gate_b2      = (const float*)d_in[19];
    const float* ln_g         = (const float*)d_in[20];
    const float* ln_b         = (const float*)d_in[21];
    const float* dec_W        = (const float*)d_in[22];
    float* out = (float*)d_out;

    cudaFuncSetAttribute(spike_recurrence_kernel,
                         cudaFuncAttributeMaxDynamicSharedMemorySize,
                         (int)sizeof(SMLayout));

    spike_recurrence_kernel<<<BB / BT, NTH, sizeof(SMLayout)>>>(
        input_ids, emb, sel_W, sel_b, patch_values,
        bind_W1, bind_b1, bind_W2, bind_b2,
        phase_embed, router_W, router_b,
        succ_W1, succ_b1, succ_W2, succ_b2,
        gate_W1, gate_b1, gate_W2, gate_b2,
        ln_g, ln_b, dec_W, out);
}